// round 12
// baseline (speedup 1.0000x reference)
#include <cuda_runtime.h>
#include <cuda_bf16.h>
#include <cstdint>

// ---------------------------------------------------------------------------
// HierarchicalAttention: two independent block-diagonal MHAs.
//   local : lqs [2,4096,1024], window 256  -> 32 windows x 16 heads
//   global: gqs [2,4096,1024], window 1024 ->  8 windows x 16 heads
// Output: concat(local_out, global_out), each [2,4096,1024] f32.
//
// R5: tcgen05 unavailable (harness PTX target is sm_103 without 'a').
// Projection GEMMs use mma.sync.m16n8k16 bf16 (HMMA) with hi/lo bf16 split
// (3 passes -> ~fp32 precision), ldmatrix fragments, cp.async double buffer.
// ---------------------------------------------------------------------------

#define D_MODEL   1024
#define D3        3072
#define N_HEADS   16
#define HD        64
#define M_ROWS    8192           // B*S = 2*4096

// Scratch (allocation-free: __device__ globals)
__device__ float g_qkv[(size_t)M_ROWS * D3];               // 100.7 MB fp32
__device__ float g_scores[134217728ULL];                   // 536.9 MB
__device__ float g_attn[(size_t)M_ROWS * D_MODEL];         // 33.6 MB
__device__ __nv_bfloat16 g_ah[(size_t)M_ROWS * D_MODEL];   // A hi (x or attn)
__device__ __nv_bfloat16 g_al[(size_t)M_ROWS * D_MODEL];   // A lo
__device__ __nv_bfloat16 g_bh[(size_t)D3 * D_MODEL];       // B hi (weights)
__device__ __nv_bfloat16 g_bl[(size_t)D3 * D_MODEL];       // B lo

// ============================================================================
// fp32 -> (bf16 hi, bf16 lo) split, vectorized
// ============================================================================
__global__ __launch_bounds__(256) void split_hi_lo(
    const float4* __restrict__ in, uint2* __restrict__ hi, uint2* __restrict__ lo, int n4)
{
    int i = blockIdx.x * 256 + threadIdx.x;
    if (i >= n4) return;
    float4 v = in[i];
    float a[4] = {v.x, v.y, v.z, v.w};
    unsigned short hb[4], lb[4];
    #pragma unroll
    for (int j = 0; j < 4; j++) {
        __nv_bfloat16 h = __float2bfloat16(a[j]);
        float r = a[j] - __bfloat162float(h);
        __nv_bfloat16 l = __float2bfloat16(r);
        hb[j] = __bfloat16_as_ushort(h);
        lb[j] = __bfloat16_as_ushort(l);
    }
    uint2 H, L;
    H.x = (uint32_t)hb[0] | ((uint32_t)hb[1] << 16);
    H.y = (uint32_t)hb[2] | ((uint32_t)hb[3] << 16);
    L.x = (uint32_t)lb[0] | ((uint32_t)lb[1] << 16);
    L.y = (uint32_t)lb[2] | ((uint32_t)lb[3] << 16);
    hi[i] = H; lo[i] = L;
}

// ============================================================================
// mma.sync helpers
// ============================================================================
__device__ __forceinline__ void mma16816(float* d, const uint32_t* a, const uint32_t* b) {
    asm volatile(
        "mma.sync.aligned.m16n8k16.row.col.f32.bf16.bf16.f32 "
        "{%0,%1,%2,%3}, {%4,%5,%6,%7}, {%8,%9}, {%0,%1,%2,%3};"
        : "+f"(d[0]), "+f"(d[1]), "+f"(d[2]), "+f"(d[3])
        : "r"(a[0]), "r"(a[1]), "r"(a[2]), "r"(a[3]), "r"(b[0]), "r"(b[1]));
}
__device__ __forceinline__ void ldsm4(uint32_t* r, uint32_t addr) {
    asm volatile("ldmatrix.sync.aligned.m8n8.x4.shared.b16 {%0,%1,%2,%3}, [%4];"
        : "=r"(r[0]), "=r"(r[1]), "=r"(r[2]), "=r"(r[3]) : "r"(addr));
}
__device__ __forceinline__ void cp_async16(uint32_t smem_dst, const void* gsrc) {
    asm volatile("cp.async.cg.shared.global [%0], [%1], 16;"
        :: "r"(smem_dst), "l"(gsrc));
}

// ============================================================================
// HMMA GEMM: C[M,N] = (Ah+Al)[M,K] @ (Bh+Bl)[N,K]^T + bias[N]   (fp32 out)
// 3 bf16 passes: Ah*Bh + Ah*Bl + Al*Bh  (al*bl dropped, ~2^-18 relative)
// CTA tile 128x128, BK=32, 8 warps (32x64 each), cp.async double buffer.
// ============================================================================
#define BK     32
#define PAD    40                       // SMEM row stride in bf16 (80 B)
#define TILE_ELEMS (128 * PAD)          // one [128][PAD] tile
// SMEM: [2 buf][4 tiles: Ah,Al,Bh,Bl][128][PAD] bf16 = 81920 B
#define SMEM_GEMM_BYTES (2 * 4 * TILE_ELEMS * 2)

__global__ __launch_bounds__(256, 1) void gemm_bf16x3(
    const __nv_bfloat16* __restrict__ Ah, const __nv_bfloat16* __restrict__ Al,
    const __nv_bfloat16* __restrict__ Bh, const __nv_bfloat16* __restrict__ Bl,
    const float* __restrict__ bias, float* __restrict__ C,
    int M, int N, int K)
{
    extern __shared__ __align__(16) __nv_bfloat16 sm[];
    const int t = threadIdx.x, lane = t & 31, wid = t >> 5;
    const int m0 = blockIdx.y * 128, n0 = blockIdx.x * 128;
    const int wm = (wid & 3) * 32;      // warp M offset within tile
    const int wn = (wid >> 2) * 64;     // warp N offset within tile

    const __nv_bfloat16* gsrc[4] = {
        Ah + (size_t)m0 * K, Al + (size_t)m0 * K,
        Bh + (size_t)n0 * K, Bl + (size_t)n0 * K };

    const uint32_t smem_base = (uint32_t)__cvta_generic_to_shared(sm);

    // loader mapping: per tile 512 16B-chunks (128 rows x 4); 2 chunks/thread/tile
    const int id0 = t * 2;

    float acc[2][8][4] = {};            // [m-tile][n-tile][frag]

    auto issue = [&](int c) {
        const int buf = c & 1;
        #pragma unroll
        for (int which = 0; which < 4; which++) {
            #pragma unroll
            for (int r = 0; r < 2; r++) {
                int id  = id0 + r;
                int row = id >> 2, cs = id & 3;
                const void* src = gsrc[which] + (size_t)row * K + c * BK + cs * 8;
                uint32_t dst = smem_base +
                    ((buf * 4 + which) * TILE_ELEMS + row * PAD + cs * 8) * 2;
                cp_async16(dst, src);
            }
        }
        asm volatile("cp.async.commit_group;");
    };

    const int nc = K / BK;
    issue(0);

    for (int c = 0; c < nc; c++) {
        const int buf = c & 1;
        if (c + 1 < nc) {
            issue(c + 1);
            asm volatile("cp.async.wait_group 1;");
        } else {
            asm volatile("cp.async.wait_group 0;");
        }
        __syncthreads();

        const uint32_t sAh = smem_base + (buf * 4 + 0) * TILE_ELEMS * 2;
        const uint32_t sAl = smem_base + (buf * 4 + 1) * TILE_ELEMS * 2;
        const uint32_t sBh = smem_base + (buf * 4 + 2) * TILE_ELEMS * 2;
        const uint32_t sBl = smem_base + (buf * 4 + 3) * TILE_ELEMS * 2;

        #pragma unroll
        for (int ks = 0; ks < 2; ks++) {            // two k16 steps per chunk
            // A fragments: row = wm + mt*16 + (lane&15), col halves via lane>>4
            uint32_t ah[2][4], al[2][4];
            #pragma unroll
            for (int mt = 0; mt < 2; mt++) {
                uint32_t off = ((wm + mt * 16 + (lane & 15)) * PAD
                                + ks * 16 + (lane >> 4) * 8) * 2;
                ldsm4(ah[mt], sAh + off);
                ldsm4(al[mt], sAl + off);
            }
            // B fragments: x4 loads two n8-tiles (b0=k-lo, b1=k-hi each)
            uint32_t bh[8][2], bl[8][2];
            #pragma unroll
            for (int np = 0; np < 4; np++) {
                int g = lane >> 3, i = lane & 7;
                uint32_t off = ((wn + np * 16 + ((g >> 1) ? 8 : 0) + i) * PAD
                                + ks * 16 + (g & 1) * 8) * 2;
                uint32_t r4[4];
                ldsm4(r4, sBh + off);
                bh[np*2+0][0] = r4[0]; bh[np*2+0][1] = r4[1];
                bh[np*2+1][0] = r4[2]; bh[np*2+1][1] = r4[3];
                ldsm4(r4, sBl + off);
                bl[np*2+0][0] = r4[0]; bl[np*2+0][1] = r4[1];
                bl[np*2+1][0] = r4[2]; bl[np*2+1][1] = r4[3];
            }
            #pragma unroll
            for (int mt = 0; mt < 2; mt++)
                #pragma unroll
                for (int nt = 0; nt < 8; nt++) {
                    mma16816(acc[mt][nt], ah[mt], bh[nt]);
                    mma16816(acc[mt][nt], ah[mt], bl[nt]);
                    mma16816(acc[mt][nt], al[mt], bh[nt]);
                }
        }
        __syncthreads();
    }

    // Epilogue: c0,c1 at (row, col), c2,c3 at (row+8, col); col = 2*(lane%4)
    #pragma unroll
    for (int mt = 0; mt < 2; mt++) {
        int row = m0 + wm + mt * 16 + (lane >> 2);
        #pragma unroll
        for (int nt = 0; nt < 8; nt++) {
            int col = n0 + wn + nt * 8 + (lane & 3) * 2;
            float b0 = bias[col], b1 = bias[col + 1];
            float2 v0 = { acc[mt][nt][0] + b0, acc[mt][nt][1] + b1 };
            float2 v1 = { acc[mt][nt][2] + b0, acc[mt][nt][3] + b1 };
            *reinterpret_cast<float2*>(&C[(size_t)row * N + col]) = v0;
            *reinterpret_cast<float2*>(&C[(size_t)(row + 8) * N + col]) = v1;
        }
    }
}

// ============================================================================
// Attention (SIMT fp32, unchanged from R2)
// ============================================================================
__global__ __launch_bounds__(128) void attn_scores(float* __restrict__ S, int W, float scale)
{
    const int p  = blockIdx.z;
    const int bw = p >> 4, h = p & 15;
    const float* Qb = g_qkv + (size_t)bw * W * D3 + h * HD;
    const float* Kb = Qb + D_MODEL;

    __shared__ float Qs[64][65];
    __shared__ float Ks[64][65];

    const int t  = threadIdx.x;
    const int tx = t & 15, ty = t >> 4;
    const int i0 = blockIdx.y * 64, j0 = blockIdx.x * 64;

    #pragma unroll
    for (int r = 0; r < 8; r++) {
        int li  = t + r * 128;
        int row = li >> 4, q = li & 15;
        float4 vq = *reinterpret_cast<const float4*>(&Qb[(size_t)(i0 + row) * D3 + q * 4]);
        Qs[row][q*4+0] = vq.x; Qs[row][q*4+1] = vq.y;
        Qs[row][q*4+2] = vq.z; Qs[row][q*4+3] = vq.w;
        float4 vk = *reinterpret_cast<const float4*>(&Kb[(size_t)(j0 + row) * D3 + q * 4]);
        Ks[row][q*4+0] = vk.x; Ks[row][q*4+1] = vk.y;
        Ks[row][q*4+2] = vk.z; Ks[row][q*4+3] = vk.w;
    }
    __syncthreads();

    float acc[8][4] = {};
    #pragma unroll
    for (int d = 0; d < 64; d++) {
        float a[8], b[4];
        #pragma unroll
        for (int u = 0; u < 8; u++) a[u] = Qs[ty*8 + u][d];
        #pragma unroll
        for (int v = 0; v < 4; v++) b[v] = Ks[tx*4 + v][d];
        #pragma unroll
        for (int u = 0; u < 8; u++)
            #pragma unroll
            for (int v = 0; v < 4; v++)
                acc[u][v] += a[u] * b[v];
    }

    float* Sp = S + (size_t)p * W * W;
    #pragma unroll
    for (int u = 0; u < 8; u++)
        #pragma unroll
        for (int v = 0; v < 4; v++)
            Sp[(size_t)(i0 + ty*8 + u) * W + (j0 + tx*4 + v)] = acc[u][v] * scale;
}

__global__ __launch_bounds__(256) void softmax_rows(float* __restrict__ S, int W)
{
    float* p = S + (size_t)blockIdx.x * W;
    const int t = threadIdx.x;
    __shared__ float red[256];

    float m = -1e30f;
    for (int j = t; j < W; j += 256) m = fmaxf(m, p[j]);
    red[t] = m; __syncthreads();
    #pragma unroll
    for (int s = 128; s > 0; s >>= 1) {
        if (t < s) red[t] = fmaxf(red[t], red[t + s]);
        __syncthreads();
    }
    m = red[0];
    __syncthreads();

    float e[4];
    float sum = 0.f;
    int k = 0;
    for (int j = t; j < W; j += 256) {
        float v = expf(p[j] - m);
        e[k++] = v;
        sum += v;
    }
    red[t] = sum; __syncthreads();
    #pragma unroll
    for (int s = 128; s > 0; s >>= 1) {
        if (t < s) red[t] += red[t + s];
        __syncthreads();
    }
    float inv = 1.f / red[0];

    k = 0;
    for (int j = t; j < W; j += 256) p[j] = e[k++] * inv;
}

__global__ __launch_bounds__(128) void attn_out(const float* __restrict__ S, int W)
{
    const int p  = blockIdx.z;
    const int bw = p >> 4, h = p & 15;
    const float* Sp = S + (size_t)p * W * W;
    const float* Vb = g_qkv + (size_t)bw * W * D3 + 2 * D_MODEL + h * HD;
    float* Ob = g_attn + (size_t)bw * W * D_MODEL + h * HD;

    __shared__ float Ps[64][17];
    __shared__ float Vs[16][65];

    const int t  = threadIdx.x;
    const int tx = t & 15, ty = t >> 4;
    const int i0 = blockIdx.y * 64;

    float acc[8][4] = {};

    for (int k0 = 0; k0 < W; k0 += 16) {
        #pragma unroll
        for (int r = 0; r < 2; r++) {
            int li  = t + r * 128;
            int row = li >> 2, q = li & 3;
            float4 vp = *reinterpret_cast<const float4*>(&Sp[(size_t)(i0 + row) * W + k0 + q * 4]);
            Ps[row][q*4+0] = vp.x; Ps[row][q*4+1] = vp.y;
            Ps[row][q*4+2] = vp.z; Ps[row][q*4+3] = vp.w;
        }
        #pragma unroll
        for (int r = 0; r < 2; r++) {
            int li  = t + r * 128;
            int row = li >> 4, q = li & 15;
            float4 vv = *reinterpret_cast<const float4*>(&Vb[(size_t)(k0 + row) * D3 + q * 4]);
            Vs[row][q*4+0] = vv.x; Vs[row][q*4+1] = vv.y;
            Vs[row][q*4+2] = vv.z; Vs[row][q*4+3] = vv.w;
        }
        __syncthreads();
        #pragma unroll
        for (int kk = 0; kk < 16; kk++) {
            float a[8], b[4];
            #pragma unroll
            for (int u = 0; u < 8; u++) a[u] = Ps[ty*8 + u][kk];
            #pragma unroll
            for (int v = 0; v < 4; v++) b[v] = Vs[kk][tx*4 + v];
            #pragma unroll
            for (int u = 0; u < 8; u++)
                #pragma unroll
                for (int v = 0; v < 4; v++)
                    acc[u][v] += a[u] * b[v];
        }
        __syncthreads();
    }

    #pragma unroll
    for (int u = 0; u < 8; u++)
        #pragma unroll
        for (int v = 0; v < 4; v++)
            Ob[(size_t)(i0 + ty*8 + u) * D_MODEL + tx*4 + v] = acc[u][v];
}

// ============================================================================
// Launch sequence (graph-capturable: kernel launches only)
// ============================================================================
static void run_branch(const float* x, const float* w_in, const float* b_in,
                       const float* w_out, const float* b_out,
                       float* out, int W,
                       float* qkv, float* scores, float* attn,
                       __nv_bfloat16* ah, __nv_bfloat16* al,
                       __nv_bfloat16* bh, __nv_bfloat16* bl)
{
    const int pairs = (M_ROWS / W) * N_HEADS;
    const float scale = 0.125f;                    // 1/sqrt(64)

    const int n4x = M_ROWS * D_MODEL / 4;
    const int n4w = D3 * D_MODEL / 4;
    const int n4o = D_MODEL * D_MODEL / 4;

    // 1) split inputs + in_proj weights to bf16 hi/lo
    split_hi_lo<<<n4x / 256, 256>>>((const float4*)x,    (uint2*)ah, (uint2*)al, n4x);
    split_hi_lo<<<n4w / 256, 256>>>((const float4*)w_in, (uint2*)bh, (uint2*)bl, n4w);
    // 2) QKV projection (HMMA): [8192,3072] = A[8192,1024] @ W[3072,1024]^T
    gemm_bf16x3<<<dim3(D3 / 128, M_ROWS / 128), 256, SMEM_GEMM_BYTES>>>(
        ah, al, bh, bl, b_in, qkv, M_ROWS, D3, D_MODEL);
    // 3) attention (SIMT fp32)
    attn_scores<<<dim3(W / 64, W / 64, pairs), 128>>>(scores, W, scale);
    softmax_rows<<<(unsigned)((size_t)pairs * W), 256>>>(scores, W);
    attn_out<<<dim3(1, W / 64, pairs), 128>>>(scores, W);
    // 4) split attn output + out_proj weights
    split_hi_lo<<<n4x / 256, 256>>>((const float4*)attn,  (uint2*)ah, (uint2*)al, n4x);
    split_hi_lo<<<n4o / 256, 256>>>((const float4*)w_out, (uint2*)bh, (uint2*)bl, n4o);
    // 5) out projection (HMMA)
    gemm_bf16x3<<<dim3(D_MODEL / 128, M_ROWS / 128), 256, SMEM_GEMM_BYTES>>>(
        ah, al, bh, bl, b_out, out, M_ROWS, D_MODEL, D_MODEL);
}

extern "C" void kernel_launch(void* const* d_in, const int* in_sizes, int n_in,
                              void* d_out, int out_size)
{
    const float* lqs   = (const float*)d_in[0];
    const float* gqs   = (const float*)d_in[1];
    const float* w_l   = (const float*)d_in[2];
    const float* b_l   = (const float*)d_in[3];
    const float* wo_l  = (const float*)d_in[4];
    const float* bo_l  = (const float*)d_in[5];
    const float* w_g   = (const float*)d_in[6];
    const float* b_g   = (const float*)d_in[7];
    const float* wo_g  = (const float*)d_in[8];
    const float* bo_g  = (const float*)d_in[9];

    float* out_l = (float*)d_out;
    float* out_g = out_l + (size_t)M_ROWS * D_MODEL;

    float *qkv = nullptr, *scores = nullptr, *attn = nullptr;
    __nv_bfloat16 *ah = nullptr, *al = nullptr, *bh = nullptr, *bl = nullptr;
    cudaGetSymbolAddress((void**)&qkv,    g_qkv);
    cudaGetSymbolAddress((void**)&scores, g_scores);
    cudaGetSymbolAddress((void**)&attn,   g_attn);
    cudaGetSymbolAddress((void**)&ah,     g_ah);
    cudaGetSymbolAddress((void**)&al,     g_al);
    cudaGetSymbolAddress((void**)&bh,     g_bh);
    cudaGetSymbolAddress((void**)&bl,     g_bl);

    cudaFuncSetAttribute(gemm_bf16x3,
                         cudaFuncAttributeMaxDynamicSharedMemorySize, SMEM_GEMM_BYTES);

    run_branch(lqs, w_l, b_l, wo_l, bo_l, out_l, 256,
               qkv, scores, attn, ah, al, bh, bl);
    run_branch(gqs, w_g, b_g, wo_g, bo_g, out_g, 1024,
               qkv, scores, attn, ah, al, bh, bl);
}

// round 13
// speedup vs baseline: 1.0319x; 1.0319x over previous
#include <cuda_runtime.h>
#include <cuda_bf16.h>
#include <cstdint>

// ---------------------------------------------------------------------------
// HierarchicalAttention: two independent block-diagonal MHAs.
//   local : lqs [2,4096,1024], window 256  -> 32 windows x 16 heads
//   global: gqs [2,4096,1024], window 1024 ->  8 windows x 16 heads
// Output: concat(local_out, global_out), each [2,4096,1024] f32.
//
// R5: tcgen05 unavailable (harness PTX target is sm_103 without 'a').
// Projection GEMMs use mma.sync.m16n8k16 bf16 (HMMA) with hi/lo bf16 split
// (3 passes -> ~fp32 precision), ldmatrix fragments, cp.async double buffer.
// ---------------------------------------------------------------------------

#define D_MODEL   1024
#define D3        3072
#define N_HEADS   16
#define HD        64
#define M_ROWS    8192           // B*S = 2*4096

// Scratch (allocation-free: __device__ globals)
__device__ float g_qkv[(size_t)M_ROWS * D3];               // 100.7 MB fp32
__device__ float g_scores[134217728ULL];                   // 536.9 MB
__device__ float g_attn[(size_t)M_ROWS * D_MODEL];         // 33.6 MB
__device__ __nv_bfloat16 g_ah[(size_t)M_ROWS * D_MODEL];   // A hi (x or attn)
__device__ __nv_bfloat16 g_al[(size_t)M_ROWS * D_MODEL];   // A lo
__device__ __nv_bfloat16 g_bh[(size_t)D3 * D_MODEL];       // B hi (weights)
__device__ __nv_bfloat16 g_bl[(size_t)D3 * D_MODEL];       // B lo

// ============================================================================
// fp32 -> (bf16 hi, bf16 lo) split, vectorized
// ============================================================================
__global__ __launch_bounds__(256) void split_hi_lo(
    const float4* __restrict__ in, uint2* __restrict__ hi, uint2* __restrict__ lo, int n4)
{
    int i = blockIdx.x * 256 + threadIdx.x;
    if (i >= n4) return;
    float4 v = in[i];
    float a[4] = {v.x, v.y, v.z, v.w};
    unsigned short hb[4], lb[4];
    #pragma unroll
    for (int j = 0; j < 4; j++) {
        __nv_bfloat16 h = __float2bfloat16(a[j]);
        float r = a[j] - __bfloat162float(h);
        __nv_bfloat16 l = __float2bfloat16(r);
        hb[j] = __bfloat16_as_ushort(h);
        lb[j] = __bfloat16_as_ushort(l);
    }
    uint2 H, L;
    H.x = (uint32_t)hb[0] | ((uint32_t)hb[1] << 16);
    H.y = (uint32_t)hb[2] | ((uint32_t)hb[3] << 16);
    L.x = (uint32_t)lb[0] | ((uint32_t)lb[1] << 16);
    L.y = (uint32_t)lb[2] | ((uint32_t)lb[3] << 16);
    hi[i] = H; lo[i] = L;
}

// ============================================================================
// mma.sync helpers
// ============================================================================
__device__ __forceinline__ void mma16816(float* d, const uint32_t* a, const uint32_t* b) {
    asm volatile(
        "mma.sync.aligned.m16n8k16.row.col.f32.bf16.bf16.f32 "
        "{%0,%1,%2,%3}, {%4,%5,%6,%7}, {%8,%9}, {%0,%1,%2,%3};"
        : "+f"(d[0]), "+f"(d[1]), "+f"(d[2]), "+f"(d[3])
        : "r"(a[0]), "r"(a[1]), "r"(a[2]), "r"(a[3]), "r"(b[0]), "r"(b[1]));
}
__device__ __forceinline__ void ldsm4(uint32_t* r, uint32_t addr) {
    asm volatile("ldmatrix.sync.aligned.m8n8.x4.shared.b16 {%0,%1,%2,%3}, [%4];"
        : "=r"(r[0]), "=r"(r[1]), "=r"(r[2]), "=r"(r[3]) : "r"(addr));
}
__device__ __forceinline__ void cp_async16(uint32_t smem_dst, const void* gsrc) {
    asm volatile("cp.async.cg.shared.global [%0], [%1], 16;"
        :: "r"(smem_dst), "l"(gsrc));
}

// ============================================================================
// HMMA GEMM: C[M,N] = (Ah+Al)[M,K] @ (Bh+Bl)[N,K]^T + bias[N]   (fp32 out)
// 3 bf16 passes: Ah*Bh + Ah*Bl + Al*Bh  (al*bl dropped, ~2^-18 relative)
// CTA tile 128x128, BK=32, 8 warps (32x64 each), cp.async double buffer.
// ============================================================================
#define BK     32
#define PAD    40                       // SMEM row stride in bf16 (80 B)
#define TILE_ELEMS (128 * PAD)          // one [128][PAD] tile
// SMEM: [2 buf][4 tiles: Ah,Al,Bh,Bl][128][PAD] bf16 = 81920 B
#define SMEM_GEMM_BYTES (2 * 4 * TILE_ELEMS * 2)

__global__ __launch_bounds__(256, 1) void gemm_bf16x3(
    const __nv_bfloat16* __restrict__ Ah, const __nv_bfloat16* __restrict__ Al,
    const __nv_bfloat16* __restrict__ Bh, const __nv_bfloat16* __restrict__ Bl,
    const float* __restrict__ bias, float* __restrict__ C,
    int M, int N, int K)
{
    extern __shared__ __align__(16) __nv_bfloat16 sm[];
    const int t = threadIdx.x, lane = t & 31, wid = t >> 5;
    const int m0 = blockIdx.y * 128, n0 = blockIdx.x * 128;
    const int wm = (wid & 3) * 32;      // warp M offset within tile
    const int wn = (wid >> 2) * 64;     // warp N offset within tile

    const __nv_bfloat16* gsrc[4] = {
        Ah + (size_t)m0 * K, Al + (size_t)m0 * K,
        Bh + (size_t)n0 * K, Bl + (size_t)n0 * K };

    const uint32_t smem_base = (uint32_t)__cvta_generic_to_shared(sm);

    // loader mapping: per tile 512 16B-chunks (128 rows x 4); 2 chunks/thread/tile
    const int id0 = t * 2;

    float acc[2][8][4] = {};            // [m-tile][n-tile][frag]

    auto issue = [&](int c) {
        const int buf = c & 1;
        #pragma unroll
        for (int which = 0; which < 4; which++) {
            #pragma unroll
            for (int r = 0; r < 2; r++) {
                int id  = id0 + r;
                int row = id >> 2, cs = id & 3;
                const void* src = gsrc[which] + (size_t)row * K + c * BK + cs * 8;
                uint32_t dst = smem_base +
                    ((buf * 4 + which) * TILE_ELEMS + row * PAD + cs * 8) * 2;
                cp_async16(dst, src);
            }
        }
        asm volatile("cp.async.commit_group;");
    };

    const int nc = K / BK;
    issue(0);

    for (int c = 0; c < nc; c++) {
        const int buf = c & 1;
        if (c + 1 < nc) {
            issue(c + 1);
            asm volatile("cp.async.wait_group 1;");
        } else {
            asm volatile("cp.async.wait_group 0;");
        }
        __syncthreads();

        const uint32_t sAh = smem_base + (buf * 4 + 0) * TILE_ELEMS * 2;
        const uint32_t sAl = smem_base + (buf * 4 + 1) * TILE_ELEMS * 2;
        const uint32_t sBh = smem_base + (buf * 4 + 2) * TILE_ELEMS * 2;
        const uint32_t sBl = smem_base + (buf * 4 + 3) * TILE_ELEMS * 2;

        #pragma unroll
        for (int ks = 0; ks < 2; ks++) {            // two k16 steps per chunk
            // A fragments: row = wm + mt*16 + (lane&15), col halves via lane>>4
            uint32_t ah[2][4], al[2][4];
            #pragma unroll
            for (int mt = 0; mt < 2; mt++) {
                uint32_t off = ((wm + mt * 16 + (lane & 15)) * PAD
                                + ks * 16 + (lane >> 4) * 8) * 2;
                ldsm4(ah[mt], sAh + off);
                ldsm4(al[mt], sAl + off);
            }
            // B fragments: x4 loads two n8-tiles (b0=k-lo, b1=k-hi each)
            uint32_t bh[8][2], bl[8][2];
            #pragma unroll
            for (int np = 0; np < 4; np++) {
                int g = lane >> 3, i = lane & 7;
                uint32_t off = ((wn + np * 16 + ((g >> 1) ? 8 : 0) + i) * PAD
                                + ks * 16 + (g & 1) * 8) * 2;
                uint32_t r4[4];
                ldsm4(r4, sBh + off);
                bh[np*2+0][0] = r4[0]; bh[np*2+0][1] = r4[1];
                bh[np*2+1][0] = r4[2]; bh[np*2+1][1] = r4[3];
                ldsm4(r4, sBl + off);
                bl[np*2+0][0] = r4[0]; bl[np*2+0][1] = r4[1];
                bl[np*2+1][0] = r4[2]; bl[np*2+1][1] = r4[3];
            }
            #pragma unroll
            for (int mt = 0; mt < 2; mt++)
                #pragma unroll
                for (int nt = 0; nt < 8; nt++) {
                    mma16816(acc[mt][nt], ah[mt], bh[nt]);
                    mma16816(acc[mt][nt], ah[mt], bl[nt]);
                    mma16816(acc[mt][nt], al[mt], bh[nt]);
                }
        }
        __syncthreads();
    }

    // Epilogue: c0,c1 at (row, col), c2,c3 at (row+8, col); col = 2*(lane%4)
    #pragma unroll
    for (int mt = 0; mt < 2; mt++) {
        int row = m0 + wm + mt * 16 + (lane >> 2);
        #pragma unroll
        for (int nt = 0; nt < 8; nt++) {
            int col = n0 + wn + nt * 8 + (lane & 3) * 2;
            float b0 = bias[col], b1 = bias[col + 1];
            float2 v0 = { acc[mt][nt][0] + b0, acc[mt][nt][1] + b1 };
            float2 v1 = { acc[mt][nt][2] + b0, acc[mt][nt][3] + b1 };
            *reinterpret_cast<float2*>(&C[(size_t)row * N + col]) = v0;
            *reinterpret_cast<float2*>(&C[(size_t)(row + 8) * N + col]) = v1;
        }
    }
}

// ============================================================================
// Attention (SIMT fp32, unchanged from R2)
// ============================================================================
__global__ __launch_bounds__(128) void attn_scores(float* __restrict__ S, int W, float scale)
{
    const int p  = blockIdx.z;
    const int bw = p >> 4, h = p & 15;
    const float* Qb = g_qkv + (size_t)bw * W * D3 + h * HD;
    const float* Kb = Qb + D_MODEL;

    __shared__ float Qs[64][65];
    __shared__ float Ks[64][65];

    const int t  = threadIdx.x;
    const int tx = t & 15, ty = t >> 4;
    const int i0 = blockIdx.y * 64, j0 = blockIdx.x * 64;

    #pragma unroll
    for (int r = 0; r < 8; r++) {
        int li  = t + r * 128;
        int row = li >> 4, q = li & 15;
        float4 vq = *reinterpret_cast<const float4*>(&Qb[(size_t)(i0 + row) * D3 + q * 4]);
        Qs[row][q*4+0] = vq.x; Qs[row][q*4+1] = vq.y;
        Qs[row][q*4+2] = vq.z; Qs[row][q*4+3] = vq.w;
        float4 vk = *reinterpret_cast<const float4*>(&Kb[(size_t)(j0 + row) * D3 + q * 4]);
        Ks[row][q*4+0] = vk.x; Ks[row][q*4+1] = vk.y;
        Ks[row][q*4+2] = vk.z; Ks[row][q*4+3] = vk.w;
    }
    __syncthreads();

    float acc[8][4] = {};
    #pragma unroll
    for (int d = 0; d < 64; d++) {
        float a[8], b[4];
        #pragma unroll
        for (int u = 0; u < 8; u++) a[u] = Qs[ty*8 + u][d];
        #pragma unroll
        for (int v = 0; v < 4; v++) b[v] = Ks[tx*4 + v][d];
        #pragma unroll
        for (int u = 0; u < 8; u++)
            #pragma unroll
            for (int v = 0; v < 4; v++)
                acc[u][v] += a[u] * b[v];
    }

    float* Sp = S + (size_t)p * W * W;
    #pragma unroll
    for (int u = 0; u < 8; u++)
        #pragma unroll
        for (int v = 0; v < 4; v++)
            Sp[(size_t)(i0 + ty*8 + u) * W + (j0 + tx*4 + v)] = acc[u][v] * scale;
}

__global__ __launch_bounds__(256) void softmax_rows(float* __restrict__ S, int W)
{
    float* p = S + (size_t)blockIdx.x * W;
    const int t = threadIdx.x;
    __shared__ float red[256];

    float m = -1e30f;
    for (int j = t; j < W; j += 256) m = fmaxf(m, p[j]);
    red[t] = m; __syncthreads();
    #pragma unroll
    for (int s = 128; s > 0; s >>= 1) {
        if (t < s) red[t] = fmaxf(red[t], red[t + s]);
        __syncthreads();
    }
    m = red[0];
    __syncthreads();

    float e[4];
    float sum = 0.f;
    int k = 0;
    for (int j = t; j < W; j += 256) {
        float v = expf(p[j] - m);
        e[k++] = v;
        sum += v;
    }
    red[t] = sum; __syncthreads();
    #pragma unroll
    for (int s = 128; s > 0; s >>= 1) {
        if (t < s) red[t] += red[t + s];
        __syncthreads();
    }
    float inv = 1.f / red[0];

    k = 0;
    for (int j = t; j < W; j += 256) p[j] = e[k++] * inv;
}

__global__ __launch_bounds__(128) void attn_out(const float* __restrict__ S, int W)
{
    const int p  = blockIdx.z;
    const int bw = p >> 4, h = p & 15;
    const float* Sp = S + (size_t)p * W * W;
    const float* Vb = g_qkv + (size_t)bw * W * D3 + 2 * D_MODEL + h * HD;
    float* Ob = g_attn + (size_t)bw * W * D_MODEL + h * HD;

    __shared__ float Ps[64][17];
    __shared__ float Vs[16][65];

    const int t  = threadIdx.x;
    const int tx = t & 15, ty = t >> 4;
    const int i0 = blockIdx.y * 64;

    float acc[8][4] = {};

    for (int k0 = 0; k0 < W; k0 += 16) {
        #pragma unroll
        for (int r = 0; r < 2; r++) {
            int li  = t + r * 128;
            int row = li >> 2, q = li & 3;
            float4 vp = *reinterpret_cast<const float4*>(&Sp[(size_t)(i0 + row) * W + k0 + q * 4]);
            Ps[row][q*4+0] = vp.x; Ps[row][q*4+1] = vp.y;
            Ps[row][q*4+2] = vp.z; Ps[row][q*4+3] = vp.w;
        }
        #pragma unroll
        for (int r = 0; r < 2; r++) {
            int li  = t + r * 128;
            int row = li >> 4, q = li & 15;
            float4 vv = *reinterpret_cast<const float4*>(&Vb[(size_t)(k0 + row) * D3 + q * 4]);
            Vs[row][q*4+0] = vv.x; Vs[row][q*4+1] = vv.y;
            Vs[row][q*4+2] = vv.z; Vs[row][q*4+3] = vv.w;
        }
        __syncthreads();
        #pragma unroll
        for (int kk = 0; kk < 16; kk++) {
            float a[8], b[4];
            #pragma unroll
            for (int u = 0; u < 8; u++) a[u] = Ps[ty*8 + u][kk];
            #pragma unroll
            for (int v = 0; v < 4; v++) b[v] = Vs[kk][tx*4 + v];
            #pragma unroll
            for (int u = 0; u < 8; u++)
                #pragma unroll
                for (int v = 0; v < 4; v++)
                    acc[u][v] += a[u] * b[v];
        }
        __syncthreads();
    }

    #pragma unroll
    for (int u = 0; u < 8; u++)
        #pragma unroll
        for (int v = 0; v < 4; v++)
            Ob[(size_t)(i0 + ty*8 + u) * D_MODEL + tx*4 + v] = acc[u][v];
}

// ============================================================================
// Launch sequence (graph-capturable: kernel launches only)
// ============================================================================
static void run_branch(const float* x, const float* w_in, const float* b_in,
                       const float* w_out, const float* b_out,
                       float* out, int W,
                       float* qkv, float* scores, float* attn,
                       __nv_bfloat16* ah, __nv_bfloat16* al,
                       __nv_bfloat16* bh, __nv_bfloat16* bl)
{
    const int pairs = (M_ROWS / W) * N_HEADS;
    const float scale = 0.125f;                    // 1/sqrt(64)

    const int n4x = M_ROWS * D_MODEL / 4;
    const int n4w = D3 * D_MODEL / 4;
    const int n4o = D_MODEL * D_MODEL / 4;

    // 1) split inputs + in_proj weights to bf16 hi/lo
    split_hi_lo<<<n4x / 256, 256>>>((const float4*)x,    (uint2*)ah, (uint2*)al, n4x);
    split_hi_lo<<<n4w / 256, 256>>>((const float4*)w_in, (uint2*)bh, (uint2*)bl, n4w);
    // 2) QKV projection (HMMA): [8192,3072] = A[8192,1024] @ W[3072,1024]^T
    gemm_bf16x3<<<dim3(D3 / 128, M_ROWS / 128), 256, SMEM_GEMM_BYTES>>>(
        ah, al, bh, bl, b_in, qkv, M_ROWS, D3, D_MODEL);
    // 3) attention (SIMT fp32)
    attn_scores<<<dim3(W / 64, W / 64, pairs), 128>>>(scores, W, scale);
    softmax_rows<<<(unsigned)((size_t)pairs * W), 256>>>(scores, W);
    attn_out<<<dim3(1, W / 64, pairs), 128>>>(scores, W);
    // 4) split attn output + out_proj weights
    split_hi_lo<<<n4x / 256, 256>>>((const float4*)attn,  (uint2*)ah, (uint2*)al, n4x);
    split_hi_lo<<<n4o / 256, 256>>>((const float4*)w_out, (uint2*)bh, (uint2*)bl, n4o);
    // 5) out projection (HMMA)
    gemm_bf16x3<<<dim3(D_MODEL / 128, M_ROWS / 128), 256, SMEM_GEMM_BYTES>>>(
        ah, al, bh, bl, b_out, out, M_ROWS, D_MODEL, D_MODEL);
}

extern "C" void kernel_launch(void* const* d_in, const int* in_sizes, int n_in,
                              void* d_out, int out_size)
{
    const float* lqs   = (const float*)d_in[0];
    const float* gqs   = (const float*)d_in[1];
    const float* w_l   = (const float*)d_in[2];
    const float* b_l   = (const float*)d_in[3];
    const float* wo_l  = (const float*)d_in[4];
    const float* bo_l  = (const float*)d_in[5];
    const float* w_g   = (const float*)d_in[6];
    const float* b_g   = (const float*)d_in[7];
    const float* wo_g  = (const float*)d_in[8];
    const float* bo_g  = (const float*)d_in[9];

    float* out_l = (float*)d_out;
    float* out_g = out_l + (size_t)M_ROWS * D_MODEL;

    float *qkv = nullptr, *scores = nullptr, *attn = nullptr;
    __nv_bfloat16 *ah = nullptr, *al = nullptr, *bh = nullptr, *bl = nullptr;
    cudaGetSymbolAddress((void**)&qkv,    g_qkv);
    cudaGetSymbolAddress((void**)&scores, g_scores);
    cudaGetSymbolAddress((void**)&attn,   g_attn);
    cudaGetSymbolAddress((void**)&ah,     g_ah);
    cudaGetSymbolAddress((void**)&al,     g_al);
    cudaGetSymbolAddress((void**)&bh,     g_bh);
    cudaGetSymbolAddress((void**)&bl,     g_bl);

    cudaFuncSetAttribute(gemm_bf16x3,
                         cudaFuncAttributeMaxDynamicSharedMemorySize, SMEM_GEMM_BYTES);

    run_branch(lqs, w_l, b_l, wo_l, bo_l, out_l, 256,
               qkv, scores, attn, ah, al, bh, bl);
    run_branch(gqs, w_g, b_g, wo_g, bo_g, out_g, 1024,
               qkv, scores, attn, ah, al, bh, bl);
}

// round 14
// speedup vs baseline: 1.0328x; 1.0009x over previous
#include <cuda_runtime.h>
#include <cuda_bf16.h>
#include <cstdint>

// ---------------------------------------------------------------------------
// HierarchicalAttention: two independent block-diagonal MHAs.
//   local : lqs [2,4096,1024], window 256  -> 32 windows x 16 heads
//   global: gqs [2,4096,1024], window 1024 ->  8 windows x 16 heads
// Output: concat(local_out, global_out), each [2,4096,1024] f32.
//
// R5: tcgen05 unavailable (harness PTX target is sm_103 without 'a').
// Projection GEMMs use mma.sync.m16n8k16 bf16 (HMMA) with hi/lo bf16 split
// (3 passes -> ~fp32 precision), ldmatrix fragments, cp.async double buffer.
// ---------------------------------------------------------------------------

#define D_MODEL   1024
#define D3        3072
#define N_HEADS   16
#define HD        64
#define M_ROWS    8192           // B*S = 2*4096

// Scratch (allocation-free: __device__ globals)
__device__ float g_qkv[(size_t)M_ROWS * D3];               // 100.7 MB fp32
__device__ float g_scores[134217728ULL];                   // 536.9 MB
__device__ float g_attn[(size_t)M_ROWS * D_MODEL];         // 33.6 MB
__device__ __nv_bfloat16 g_ah[(size_t)M_ROWS * D_MODEL];   // A hi (x or attn)
__device__ __nv_bfloat16 g_al[(size_t)M_ROWS * D_MODEL];   // A lo
__device__ __nv_bfloat16 g_bh[(size_t)D3 * D_MODEL];       // B hi (weights)
__device__ __nv_bfloat16 g_bl[(size_t)D3 * D_MODEL];       // B lo

// ============================================================================
// fp32 -> (bf16 hi, bf16 lo) split, vectorized
// ============================================================================
__global__ __launch_bounds__(256) void split_hi_lo(
    const float4* __restrict__ in, uint2* __restrict__ hi, uint2* __restrict__ lo, int n4)
{
    int i = blockIdx.x * 256 + threadIdx.x;
    if (i >= n4) return;
    float4 v = in[i];
    float a[4] = {v.x, v.y, v.z, v.w};
    unsigned short hb[4], lb[4];
    #pragma unroll
    for (int j = 0; j < 4; j++) {
        __nv_bfloat16 h = __float2bfloat16(a[j]);
        float r = a[j] - __bfloat162float(h);
        __nv_bfloat16 l = __float2bfloat16(r);
        hb[j] = __bfloat16_as_ushort(h);
        lb[j] = __bfloat16_as_ushort(l);
    }
    uint2 H, L;
    H.x = (uint32_t)hb[0] | ((uint32_t)hb[1] << 16);
    H.y = (uint32_t)hb[2] | ((uint32_t)hb[3] << 16);
    L.x = (uint32_t)lb[0] | ((uint32_t)lb[1] << 16);
    L.y = (uint32_t)lb[2] | ((uint32_t)lb[3] << 16);
    hi[i] = H; lo[i] = L;
}

// ============================================================================
// mma.sync helpers
// ============================================================================
__device__ __forceinline__ void mma16816(float* d, const uint32_t* a, const uint32_t* b) {
    asm volatile(
        "mma.sync.aligned.m16n8k16.row.col.f32.bf16.bf16.f32 "
        "{%0,%1,%2,%3}, {%4,%5,%6,%7}, {%8,%9}, {%0,%1,%2,%3};"
        : "+f"(d[0]), "+f"(d[1]), "+f"(d[2]), "+f"(d[3])
        : "r"(a[0]), "r"(a[1]), "r"(a[2]), "r"(a[3]), "r"(b[0]), "r"(b[1]));
}
__device__ __forceinline__ void ldsm4(uint32_t* r, uint32_t addr) {
    asm volatile("ldmatrix.sync.aligned.m8n8.x4.shared.b16 {%0,%1,%2,%3}, [%4];"
        : "=r"(r[0]), "=r"(r[1]), "=r"(r[2]), "=r"(r[3]) : "r"(addr));
}
__device__ __forceinline__ void cp_async16(uint32_t smem_dst, const void* gsrc) {
    asm volatile("cp.async.cg.shared.global [%0], [%1], 16;"
        :: "r"(smem_dst), "l"(gsrc));
}

// ============================================================================
// HMMA GEMM: C[M,N] = (Ah+Al)[M,K] @ (Bh+Bl)[N,K]^T + bias[N]   (fp32 out)
// 3 bf16 passes: Ah*Bh + Ah*Bl + Al*Bh  (al*bl dropped, ~2^-18 relative)
// CTA tile 128x128, BK=32, 8 warps (32x64 each), cp.async double buffer.
// ============================================================================
#define BK     32
#define PAD    40                       // SMEM row stride in bf16 (80 B)
#define TILE_ELEMS (128 * PAD)          // one [128][PAD] tile
// SMEM: [2 buf][4 tiles: Ah,Al,Bh,Bl][128][PAD] bf16 = 81920 B
#define SMEM_GEMM_BYTES (2 * 4 * TILE_ELEMS * 2)

__global__ __launch_bounds__(256, 1) void gemm_bf16x3(
    const __nv_bfloat16* __restrict__ Ah, const __nv_bfloat16* __restrict__ Al,
    const __nv_bfloat16* __restrict__ Bh, const __nv_bfloat16* __restrict__ Bl,
    const float* __restrict__ bias, float* __restrict__ C,
    int M, int N, int K)
{
    extern __shared__ __align__(16) __nv_bfloat16 sm[];
    const int t = threadIdx.x, lane = t & 31, wid = t >> 5;
    const int m0 = blockIdx.y * 128, n0 = blockIdx.x * 128;
    const int wm = (wid & 3) * 32;      // warp M offset within tile
    const int wn = (wid >> 2) * 64;     // warp N offset within tile

    const __nv_bfloat16* gsrc[4] = {
        Ah + (size_t)m0 * K, Al + (size_t)m0 * K,
        Bh + (size_t)n0 * K, Bl + (size_t)n0 * K };

    const uint32_t smem_base = (uint32_t)__cvta_generic_to_shared(sm);

    // loader mapping: per tile 512 16B-chunks (128 rows x 4); 2 chunks/thread/tile
    const int id0 = t * 2;

    float acc[2][8][4] = {};            // [m-tile][n-tile][frag]

    auto issue = [&](int c) {
        const int buf = c & 1;
        #pragma unroll
        for (int which = 0; which < 4; which++) {
            #pragma unroll
            for (int r = 0; r < 2; r++) {
                int id  = id0 + r;
                int row = id >> 2, cs = id & 3;
                const void* src = gsrc[which] + (size_t)row * K + c * BK + cs * 8;
                uint32_t dst = smem_base +
                    ((buf * 4 + which) * TILE_ELEMS + row * PAD + cs * 8) * 2;
                cp_async16(dst, src);
            }
        }
        asm volatile("cp.async.commit_group;");
    };

    const int nc = K / BK;
    issue(0);

    for (int c = 0; c < nc; c++) {
        const int buf = c & 1;
        if (c + 1 < nc) {
            issue(c + 1);
            asm volatile("cp.async.wait_group 1;");
        } else {
            asm volatile("cp.async.wait_group 0;");
        }
        __syncthreads();

        const uint32_t sAh = smem_base + (buf * 4 + 0) * TILE_ELEMS * 2;
        const uint32_t sAl = smem_base + (buf * 4 + 1) * TILE_ELEMS * 2;
        const uint32_t sBh = smem_base + (buf * 4 + 2) * TILE_ELEMS * 2;
        const uint32_t sBl = smem_base + (buf * 4 + 3) * TILE_ELEMS * 2;

        #pragma unroll
        for (int ks = 0; ks < 2; ks++) {            // two k16 steps per chunk
            // A fragments: row = wm + mt*16 + (lane&15), col halves via lane>>4
            uint32_t ah[2][4], al[2][4];
            #pragma unroll
            for (int mt = 0; mt < 2; mt++) {
                uint32_t off = ((wm + mt * 16 + (lane & 15)) * PAD
                                + ks * 16 + (lane >> 4) * 8) * 2;
                ldsm4(ah[mt], sAh + off);
                ldsm4(al[mt], sAl + off);
            }
            // B fragments: x4 loads two n8-tiles (b0=k-lo, b1=k-hi each)
            uint32_t bh[8][2], bl[8][2];
            #pragma unroll
            for (int np = 0; np < 4; np++) {
                int g = lane >> 3, i = lane & 7;
                uint32_t off = ((wn + np * 16 + ((g >> 1) ? 8 : 0) + i) * PAD
                                + ks * 16 + (g & 1) * 8) * 2;
                uint32_t r4[4];
                ldsm4(r4, sBh + off);
                bh[np*2+0][0] = r4[0]; bh[np*2+0][1] = r4[1];
                bh[np*2+1][0] = r4[2]; bh[np*2+1][1] = r4[3];
                ldsm4(r4, sBl + off);
                bl[np*2+0][0] = r4[0]; bl[np*2+0][1] = r4[1];
                bl[np*2+1][0] = r4[2]; bl[np*2+1][1] = r4[3];
            }
            #pragma unroll
            for (int mt = 0; mt < 2; mt++)
                #pragma unroll
                for (int nt = 0; nt < 8; nt++) {
                    mma16816(acc[mt][nt], ah[mt], bh[nt]);
                    mma16816(acc[mt][nt], ah[mt], bl[nt]);
                    mma16816(acc[mt][nt], al[mt], bh[nt]);
                }
        }
        __syncthreads();
    }

    // Epilogue: c0,c1 at (row, col), c2,c3 at (row+8, col); col = 2*(lane%4)
    #pragma unroll
    for (int mt = 0; mt < 2; mt++) {
        int row = m0 + wm + mt * 16 + (lane >> 2);
        #pragma unroll
        for (int nt = 0; nt < 8; nt++) {
            int col = n0 + wn + nt * 8 + (lane & 3) * 2;
            float b0 = bias[col], b1 = bias[col + 1];
            float2 v0 = { acc[mt][nt][0] + b0, acc[mt][nt][1] + b1 };
            float2 v1 = { acc[mt][nt][2] + b0, acc[mt][nt][3] + b1 };
            *reinterpret_cast<float2*>(&C[(size_t)row * N + col]) = v0;
            *reinterpret_cast<float2*>(&C[(size_t)(row + 8) * N + col]) = v1;
        }
    }
}

// ============================================================================
// Attention (SIMT fp32, unchanged from R2)
// ============================================================================
__global__ __launch_bounds__(128) void attn_scores(float* __restrict__ S, int W, float scale)
{
    const int p  = blockIdx.z;
    const int bw = p >> 4, h = p & 15;
    const float* Qb = g_qkv + (size_t)bw * W * D3 + h * HD;
    const float* Kb = Qb + D_MODEL;

    __shared__ float Qs[64][65];
    __shared__ float Ks[64][65];

    const int t  = threadIdx.x;
    const int tx = t & 15, ty = t >> 4;
    const int i0 = blockIdx.y * 64, j0 = blockIdx.x * 64;

    #pragma unroll
    for (int r = 0; r < 8; r++) {
        int li  = t + r * 128;
        int row = li >> 4, q = li & 15;
        float4 vq = *reinterpret_cast<const float4*>(&Qb[(size_t)(i0 + row) * D3 + q * 4]);
        Qs[row][q*4+0] = vq.x; Qs[row][q*4+1] = vq.y;
        Qs[row][q*4+2] = vq.z; Qs[row][q*4+3] = vq.w;
        float4 vk = *reinterpret_cast<const float4*>(&Kb[(size_t)(j0 + row) * D3 + q * 4]);
        Ks[row][q*4+0] = vk.x; Ks[row][q*4+1] = vk.y;
        Ks[row][q*4+2] = vk.z; Ks[row][q*4+3] = vk.w;
    }
    __syncthreads();

    float acc[8][4] = {};
    #pragma unroll
    for (int d = 0; d < 64; d++) {
        float a[8], b[4];
        #pragma unroll
        for (int u = 0; u < 8; u++) a[u] = Qs[ty*8 + u][d];
        #pragma unroll
        for (int v = 0; v < 4; v++) b[v] = Ks[tx*4 + v][d];
        #pragma unroll
        for (int u = 0; u < 8; u++)
            #pragma unroll
            for (int v = 0; v < 4; v++)
                acc[u][v] += a[u] * b[v];
    }

    float* Sp = S + (size_t)p * W * W;
    #pragma unroll
    for (int u = 0; u < 8; u++)
        #pragma unroll
        for (int v = 0; v < 4; v++)
            Sp[(size_t)(i0 + ty*8 + u) * W + (j0 + tx*4 + v)] = acc[u][v] * scale;
}

__global__ __launch_bounds__(256) void softmax_rows(float* __restrict__ S, int W)
{
    float* p = S + (size_t)blockIdx.x * W;
    const int t = threadIdx.x;
    __shared__ float red[256];

    float m = -1e30f;
    for (int j = t; j < W; j += 256) m = fmaxf(m, p[j]);
    red[t] = m; __syncthreads();
    #pragma unroll
    for (int s = 128; s > 0; s >>= 1) {
        if (t < s) red[t] = fmaxf(red[t], red[t + s]);
        __syncthreads();
    }
    m = red[0];
    __syncthreads();

    float e[4];
    float sum = 0.f;
    int k = 0;
    for (int j = t; j < W; j += 256) {
        float v = expf(p[j] - m);
        e[k++] = v;
        sum += v;
    }
    red[t] = sum; __syncthreads();
    #pragma unroll
    for (int s = 128; s > 0; s >>= 1) {
        if (t < s) red[t] += red[t + s];
        __syncthreads();
    }
    float inv = 1.f / red[0];

    k = 0;
    for (int j = t; j < W; j += 256) p[j] = e[k++] * inv;
}

__global__ __launch_bounds__(128) void attn_out(const float* __restrict__ S, int W)
{
    const int p  = blockIdx.z;
    const int bw = p >> 4, h = p & 15;
    const float* Sp = S + (size_t)p * W * W;
    const float* Vb = g_qkv + (size_t)bw * W * D3 + 2 * D_MODEL + h * HD;
    float* Ob = g_attn + (size_t)bw * W * D_MODEL + h * HD;

    __shared__ float Ps[64][17];
    __shared__ float Vs[16][65];

    const int t  = threadIdx.x;
    const int tx = t & 15, ty = t >> 4;
    const int i0 = blockIdx.y * 64;

    float acc[8][4] = {};

    for (int k0 = 0; k0 < W; k0 += 16) {
        #pragma unroll
        for (int r = 0; r < 2; r++) {
            int li  = t + r * 128;
            int row = li >> 2, q = li & 3;
            float4 vp = *reinterpret_cast<const float4*>(&Sp[(size_t)(i0 + row) * W + k0 + q * 4]);
            Ps[row][q*4+0] = vp.x; Ps[row][q*4+1] = vp.y;
            Ps[row][q*4+2] = vp.z; Ps[row][q*4+3] = vp.w;
        }
        #pragma unroll
        for (int r = 0; r < 2; r++) {
            int li  = t + r * 128;
            int row = li >> 4, q = li & 15;
            float4 vv = *reinterpret_cast<const float4*>(&Vb[(size_t)(k0 + row) * D3 + q * 4]);
            Vs[row][q*4+0] = vv.x; Vs[row][q*4+1] = vv.y;
            Vs[row][q*4+2] = vv.z; Vs[row][q*4+3] = vv.w;
        }
        __syncthreads();
        #pragma unroll
        for (int kk = 0; kk < 16; kk++) {
            float a[8], b[4];
            #pragma unroll
            for (int u = 0; u < 8; u++) a[u] = Ps[ty*8 + u][kk];
            #pragma unroll
            for (int v = 0; v < 4; v++) b[v] = Vs[kk][tx*4 + v];
            #pragma unroll
            for (int u = 0; u < 8; u++)
                #pragma unroll
                for (int v = 0; v < 4; v++)
                    acc[u][v] += a[u] * b[v];
        }
        __syncthreads();
    }

    #pragma unroll
    for (int u = 0; u < 8; u++)
        #pragma unroll
        for (int v = 0; v < 4; v++)
            Ob[(size_t)(i0 + ty*8 + u) * D_MODEL + tx*4 + v] = acc[u][v];
}

// ============================================================================
// Launch sequence (graph-capturable: kernel launches only)
// ============================================================================
static void run_branch(const float* x, const float* w_in, const float* b_in,
                       const float* w_out, const float* b_out,
                       float* out, int W,
                       float* qkv, float* scores, float* attn,
                       __nv_bfloat16* ah, __nv_bfloat16* al,
                       __nv_bfloat16* bh, __nv_bfloat16* bl)
{
    const int pairs = (M_ROWS / W) * N_HEADS;
    const float scale = 0.125f;                    // 1/sqrt(64)

    const int n4x = M_ROWS * D_MODEL / 4;
    const int n4w = D3 * D_MODEL / 4;
    const int n4o = D_MODEL * D_MODEL / 4;

    // 1) split inputs + in_proj weights to bf16 hi/lo
    split_hi_lo<<<n4x / 256, 256>>>((const float4*)x,    (uint2*)ah, (uint2*)al, n4x);
    split_hi_lo<<<n4w / 256, 256>>>((const float4*)w_in, (uint2*)bh, (uint2*)bl, n4w);
    // 2) QKV projection (HMMA): [8192,3072] = A[8192,1024] @ W[3072,1024]^T
    gemm_bf16x3<<<dim3(D3 / 128, M_ROWS / 128), 256, SMEM_GEMM_BYTES>>>(
        ah, al, bh, bl, b_in, qkv, M_ROWS, D3, D_MODEL);
    // 3) attention (SIMT fp32)
    attn_scores<<<dim3(W / 64, W / 64, pairs), 128>>>(scores, W, scale);
    softmax_rows<<<(unsigned)((size_t)pairs * W), 256>>>(scores, W);
    attn_out<<<dim3(1, W / 64, pairs), 128>>>(scores, W);
    // 4) split attn output + out_proj weights
    split_hi_lo<<<n4x / 256, 256>>>((const float4*)attn,  (uint2*)ah, (uint2*)al, n4x);
    split_hi_lo<<<n4o / 256, 256>>>((const float4*)w_out, (uint2*)bh, (uint2*)bl, n4o);
    // 5) out projection (HMMA)
    gemm_bf16x3<<<dim3(D_MODEL / 128, M_ROWS / 128), 256, SMEM_GEMM_BYTES>>>(
        ah, al, bh, bl, b_out, out, M_ROWS, D_MODEL, D_MODEL);
}

extern "C" void kernel_launch(void* const* d_in, const int* in_sizes, int n_in,
                              void* d_out, int out_size)
{
    const float* lqs   = (const float*)d_in[0];
    const float* gqs   = (const float*)d_in[1];
    const float* w_l   = (const float*)d_in[2];
    const float* b_l   = (const float*)d_in[3];
    const float* wo_l  = (const float*)d_in[4];
    const float* bo_l  = (const float*)d_in[5];
    const float* w_g   = (const float*)d_in[6];
    const float* b_g   = (const float*)d_in[7];
    const float* wo_g  = (const float*)d_in[8];
    const float* bo_g  = (const float*)d_in[9];

    float* out_l = (float*)d_out;
    float* out_g = out_l + (size_t)M_ROWS * D_MODEL;

    float *qkv = nullptr, *scores = nullptr, *attn = nullptr;
    __nv_bfloat16 *ah = nullptr, *al = nullptr, *bh = nullptr, *bl = nullptr;
    cudaGetSymbolAddress((void**)&qkv,    g_qkv);
    cudaGetSymbolAddress((void**)&scores, g_scores);
    cudaGetSymbolAddress((void**)&attn,   g_attn);
    cudaGetSymbolAddress((void**)&ah,     g_ah);
    cudaGetSymbolAddress((void**)&al,     g_al);
    cudaGetSymbolAddress((void**)&bh,     g_bh);
    cudaGetSymbolAddress((void**)&bl,     g_bl);

    cudaFuncSetAttribute(gemm_bf16x3,
                         cudaFuncAttributeMaxDynamicSharedMemorySize, SMEM_GEMM_BYTES);

    run_branch(lqs, w_l, b_l, wo_l, bo_l, out_l, 256,
               qkv, scores, attn, ah, al, bh, bl);
    run_branch(gqs, w_g, b_g, wo_g, bo_g, out_g, 1024,
               qkv, scores, attn, ah, al, bh, bl);
}